// round 8
// baseline (speedup 1.0000x reference)
#include <cuda_runtime.h>
#include <cstdint>

// DangoCutouts: 16 x (3,512,512) fp32 outputs from one (3,4096,4096) image.
// grid.y==0 : overview — one bilinear gather serves images 0,1,2,3.
// grid.y>=1 : random crops (crop 0 grayed), PROCESSED IN offy-SORTED ORDER so
//             temporally adjacent crops overlap spatially -> L2 reuse.
// 2 output pixels per thread in y; streaming stores (__stcs).

#define H 4096
#define W 4096
#define CUT 512
#define CH_STRIDE (4096u * 4096u)
#define PLANE (CUT * CUT)
#define N_INNER 12

struct Taps { int x0, x1; float wx; };

__device__ __forceinline__ Taps tap1d(int o, int size, float s, float sc, int i)
{
    float f = (float)o + (((float)i + 0.5f) * sc - 0.5f);
    f = fminf(fmaxf(f, (float)o), (float)o + s - 1.0f);
    Taps t;
    t.x0 = (int)floorf(f);
    t.x1 = min(t.x0 + 1, o + size - 1);
    t.wx = f - (float)t.x0;
    return t;
}

__global__ __launch_bounds__(256)
void dango_cutouts_kernel(const float* __restrict__ img,
                          const int*   __restrict__ sizes,
                          const int*   __restrict__ offy,
                          const int*   __restrict__ offx,
                          float*       __restrict__ out)
{
    const int p  = blockIdx.x * blockDim.x + threadIdx.x;   // 0 .. 512*256-1
    const int g  = blockIdx.y;                               // 0 .. 12
    const int xo = p & 511;                                  // lane-consecutive x
    const int yo = (p >> 9) << 1;                            // first of 2 rows

    int oy, ox, sz, j = -1;
    if (g == 0) { oy = 0; ox = 0; sz = 4096; }
    else {
        // Remap processing rank -> crop index, sorted by offy ascending.
        // Redundant per-thread 12-element insertion sort (~100 cycles, ALU noise).
        int key[N_INNER];
        unsigned char perm[N_INNER];
#pragma unroll
        for (int k = 0; k < N_INNER; ++k) {
            key[k]  = __ldg(offy + k);
            perm[k] = (unsigned char)k;
        }
#pragma unroll
        for (int a = 1; a < N_INNER; ++a) {
            const int kv = key[a];
            const unsigned char pv = perm[a];
            int b = a - 1;
#pragma unroll
            for (int it = 0; it < N_INNER - 1; ++it) {
                if (b >= 0 && key[b] > kv) {
                    key[b + 1]  = key[b];
                    perm[b + 1] = perm[b];
                    --b;
                }
            }
            key[b + 1]  = kv;
            perm[b + 1] = pv;
        }
        j  = perm[g - 1];
        oy = key[g - 1];            // == offy[j]
        ox = __ldg(offx  + j);
        sz = __ldg(sizes + j);
    }

    const float s  = (float)sz;
    const float sc = s * (1.0f / 512.0f);   // exact pow2 scale

    const Taps tx = tap1d(ox, sz, s, sc, xo);
    const Taps ya = tap1d(oy, sz, s, sc, yo);
    const Taps yb = tap1d(oy, sz, s, sc, yo + 1);

    const size_t r0a = (size_t)ya.x0 * W;
    const size_t r1a = (size_t)ya.x1 * W;
    const size_t r0b = (size_t)yb.x0 * W;
    const size_t r1b = (size_t)yb.x1 * W;

    float va[3], vb[3];
#pragma unroll
    for (int c = 0; c < 3; ++c) {
        const float* base = img + (size_t)c * CH_STRIDE;
        const float a00 = __ldg(base + r0a + tx.x0);
        const float a01 = __ldg(base + r0a + tx.x1);
        const float a10 = __ldg(base + r1a + tx.x0);
        const float a11 = __ldg(base + r1a + tx.x1);
        const float b00 = __ldg(base + r0b + tx.x0);
        const float b01 = __ldg(base + r0b + tx.x1);
        const float b10 = __ldg(base + r1b + tx.x0);
        const float b11 = __ldg(base + r1b + tx.x1);

        const float atop = a00 + (a01 - a00) * tx.wx;
        const float abot = a10 + (a11 - a10) * tx.wx;
        const float btop = b00 + (b01 - b00) * tx.wx;
        const float bbot = b10 + (b11 - b10) * tx.wx;
        va[c] = atop + (abot - atop) * ya.wx;
        vb[c] = btop + (bbot - btop) * yb.wx;
    }

    if (g == 0) {
        const float ga = 0.2989f * va[0] + 0.587f * va[1] + 0.114f * va[2];
        const float gb = 0.2989f * vb[0] + 0.587f * vb[1] + 0.114f * vb[2];
        const size_t rowa = (size_t)yo * CUT;
        const size_t rowb = rowa + CUT;
        const size_t pfa = rowa + xo,  pra = rowa + (511 - xo);
        const size_t pfb = rowb + xo,  prb = rowb + (511 - xo);
#pragma unroll
        for (int c = 0; c < 3; ++c) {
            const size_t cp = (size_t)c * PLANE;
            __stcs(out + 0 * PLANE + cp + pfa, va[c]);   // img0 full
            __stcs(out + 0 * PLANE + cp + pfb, vb[c]);
            __stcs(out + 3 * PLANE + cp + pfa, ga);      // img1 gray
            __stcs(out + 3 * PLANE + cp + pfb, gb);
            __stcs(out + 6 * PLANE + cp + pra, va[c]);   // img2 flip
            __stcs(out + 6 * PLANE + cp + prb, vb[c]);
            __stcs(out + 9 * PLANE + cp + pra, ga);      // img3 gray-flip
            __stcs(out + 9 * PLANE + cp + prb, gb);
        }
    } else {
        if (j == 0) {   // crop 0 (original index) is grayed
            const float ga = 0.2989f * va[0] + 0.587f * va[1] + 0.114f * va[2];
            const float gb = 0.2989f * vb[0] + 0.587f * vb[1] + 0.114f * vb[2];
            va[0] = va[1] = va[2] = ga;
            vb[0] = vb[1] = vb[2] = gb;
        }
        const size_t obase = ((size_t)(j + 4) * 3) * PLANE + (size_t)yo * CUT + xo;
#pragma unroll
        for (int c = 0; c < 3; ++c) {
            __stcs(out + obase + (size_t)c * PLANE, va[c]);
            __stcs(out + obase + (size_t)c * PLANE + CUT, vb[c]);
        }
    }
}

extern "C" void kernel_launch(void* const* d_in, const int* in_sizes, int n_in,
                              void* d_out, int out_size)
{
    const float* img   = (const float*)d_in[0];
    // d_in[1] = t (unused)
    const int*   sizes = (const int*)d_in[2];
    const int*   offy  = (const int*)d_in[3];
    const int*   offx  = (const int*)d_in[4];
    float*       out   = (float*)d_out;

    dim3 block(256, 1, 1);
    dim3 grid((PLANE / 2) / 256, 13, 1);
    dango_cutouts_kernel<<<grid, block>>>(img, sizes, offy, offx, out);
}

// round 10
// speedup vs baseline: 2.8810x; 2.8810x over previous
#include <cuda_runtime.h>
#include <cstdint>

// DangoCutouts: 16 x (3,512,512) fp32 outputs from one (3,4096,4096) image.
// grid.y==0 : overview — one bilinear gather serves images 0,1,2,3.
// grid.y>=1 : random crops (crop 0 grayed), processed in offy-sorted order
//             (register-only rank select — NO local-memory arrays).
// 2 output pixels per thread in y; streaming stores (__stcs).

#define H 4096
#define W 4096
#define CUT 512
#define CH_STRIDE (4096u * 4096u)
#define PLANE (CUT * CUT)
#define N_INNER 12

struct Taps { int x0, x1; float wx; };

__device__ __forceinline__ Taps tap1d(int o, int size, float s, float sc, int i)
{
    float f = (float)o + (((float)i + 0.5f) * sc - 0.5f);
    f = fminf(fmaxf(f, (float)o), (float)o + s - 1.0f);
    Taps t;
    t.x0 = (int)floorf(f);
    t.x1 = min(t.x0 + 1, o + size - 1);
    t.wx = f - (float)t.x0;
    return t;
}

__global__ __launch_bounds__(256)
void dango_cutouts_kernel(const float* __restrict__ img,
                          const int*   __restrict__ sizes,
                          const int*   __restrict__ offy,
                          const int*   __restrict__ offx,
                          float*       __restrict__ out)
{
    const int p  = blockIdx.x * blockDim.x + threadIdx.x;   // 0 .. 512*256-1
    const int g  = blockIdx.y;                               // 0 .. 12
    const int xo = p & 511;                                  // lane-consecutive x
    const int yo = (p >> 9) << 1;                            // first of 2 rows

    int oy, ox, sz, j = -1;
    if (g == 0) { oy = 0; ox = 0; sz = 4096; }
    else {
        // Processing rank (g-1) -> crop index j, sorted by offy ascending.
        // rank(cand) = #{k : offy[k] < offy[cand], tie -> lower k first}.
        // Fully unrolled, register-only: no arrays, no local memory.
        const int target = g - 1;
#pragma unroll
        for (int cand = 0; cand < N_INNER; ++cand) {
            const int oyc = __ldg(offy + cand);
            int rank = 0;
#pragma unroll
            for (int k = 0; k < N_INNER; ++k) {
                const int oyk = __ldg(offy + k);
                rank += (oyk < oyc) || (oyk == oyc && k < cand);
            }
            if (rank == target) j = cand;
        }
        oy = __ldg(offy  + j);
        ox = __ldg(offx  + j);
        sz = __ldg(sizes + j);
    }

    const float s  = (float)sz;
    const float sc = s * (1.0f / 512.0f);   // exact pow2 scale

    const Taps tx = tap1d(ox, sz, s, sc, xo);
    const Taps ya = tap1d(oy, sz, s, sc, yo);
    const Taps yb = tap1d(oy, sz, s, sc, yo + 1);

    const size_t r0a = (size_t)ya.x0 * W;
    const size_t r1a = (size_t)ya.x1 * W;
    const size_t r0b = (size_t)yb.x0 * W;
    const size_t r1b = (size_t)yb.x1 * W;

    float va[3], vb[3];
#pragma unroll
    for (int c = 0; c < 3; ++c) {
        const float* base = img + (size_t)c * CH_STRIDE;
        const float a00 = __ldg(base + r0a + tx.x0);
        const float a01 = __ldg(base + r0a + tx.x1);
        const float a10 = __ldg(base + r1a + tx.x0);
        const float a11 = __ldg(base + r1a + tx.x1);
        const float b00 = __ldg(base + r0b + tx.x0);
        const float b01 = __ldg(base + r0b + tx.x1);
        const float b10 = __ldg(base + r1b + tx.x0);
        const float b11 = __ldg(base + r1b + tx.x1);

        const float atop = a00 + (a01 - a00) * tx.wx;
        const float abot = a10 + (a11 - a10) * tx.wx;
        const float btop = b00 + (b01 - b00) * tx.wx;
        const float bbot = b10 + (b11 - b10) * tx.wx;
        va[c] = atop + (abot - atop) * ya.wx;
        vb[c] = btop + (bbot - btop) * yb.wx;
    }

    if (g == 0) {
        const float ga = 0.2989f * va[0] + 0.587f * va[1] + 0.114f * va[2];
        const float gb = 0.2989f * vb[0] + 0.587f * vb[1] + 0.114f * vb[2];
        const size_t rowa = (size_t)yo * CUT;
        const size_t rowb = rowa + CUT;
        const size_t pfa = rowa + xo,  pra = rowa + (511 - xo);
        const size_t pfb = rowb + xo,  prb = rowb + (511 - xo);
#pragma unroll
        for (int c = 0; c < 3; ++c) {
            const size_t cp = (size_t)c * PLANE;
            __stcs(out + 0 * PLANE + cp + pfa, va[c]);   // img0 full
            __stcs(out + 0 * PLANE + cp + pfb, vb[c]);
            __stcs(out + 3 * PLANE + cp + pfa, ga);      // img1 gray
            __stcs(out + 3 * PLANE + cp + pfb, gb);
            __stcs(out + 6 * PLANE + cp + pra, va[c]);   // img2 flip
            __stcs(out + 6 * PLANE + cp + prb, vb[c]);
            __stcs(out + 9 * PLANE + cp + pra, ga);      // img3 gray-flip
            __stcs(out + 9 * PLANE + cp + prb, gb);
        }
    } else {
        if (j == 0) {   // crop 0 (original index) is grayed
            const float ga = 0.2989f * va[0] + 0.587f * va[1] + 0.114f * va[2];
            const float gb = 0.2989f * vb[0] + 0.587f * vb[1] + 0.114f * vb[2];
            va[0] = va[1] = va[2] = ga;
            vb[0] = vb[1] = vb[2] = gb;
        }
        const size_t obase = ((size_t)(j + 4) * 3) * PLANE + (size_t)yo * CUT + xo;
#pragma unroll
        for (int c = 0; c < 3; ++c) {
            __stcs(out + obase + (size_t)c * PLANE, va[c]);
            __stcs(out + obase + (size_t)c * PLANE + CUT, vb[c]);
        }
    }
}

extern "C" void kernel_launch(void* const* d_in, const int* in_sizes, int n_in,
                              void* d_out, int out_size)
{
    const float* img   = (const float*)d_in[0];
    // d_in[1] = t (unused)
    const int*   sizes = (const int*)d_in[2];
    const int*   offy  = (const int*)d_in[3];
    const int*   offx  = (const int*)d_in[4];
    float*       out   = (float*)d_out;

    dim3 block(256, 1, 1);
    dim3 grid((PLANE / 2) / 256, 13, 1);
    dango_cutouts_kernel<<<grid, block>>>(img, sizes, offy, offx, out);
}

// round 11
// speedup vs baseline: 3.2605x; 1.1317x over previous
#include <cuda_runtime.h>
#include <cstdint>

// DangoCutouts: 16 x (3,512,512) fp32 outputs from one (3,4096,4096) image.
// grid.y==0 : overview — one bilinear gather serves images 0,1,2,3.
// grid.y>=1 : random crops (crop 0 grayed), processed in offy-sorted order.
//             Permutation computed ONCE PER BLOCK in smem (threads 0..11 in
//             parallel) — zero per-thread main-path cost, no local memory.
// 2 output pixels per thread in y; streaming stores (__stcs).

#define H 4096
#define W 4096
#define CUT 512
#define CH_STRIDE (4096u * 4096u)
#define PLANE (CUT * CUT)
#define N_INNER 12

struct Taps { int x0, x1; float wx; };

__device__ __forceinline__ Taps tap1d(int o, int size, float s, float sc, int i)
{
    float f = (float)o + (((float)i + 0.5f) * sc - 0.5f);
    f = fminf(fmaxf(f, (float)o), (float)o + s - 1.0f);
    Taps t;
    t.x0 = (int)floorf(f);
    t.x1 = min(t.x0 + 1, o + size - 1);
    t.wx = f - (float)t.x0;
    return t;
}

__global__ __launch_bounds__(256)
void dango_cutouts_kernel(const float* __restrict__ img,
                          const int*   __restrict__ sizes,
                          const int*   __restrict__ offy,
                          const int*   __restrict__ offx,
                          float*       __restrict__ out)
{
    const int p  = blockIdx.x * blockDim.x + threadIdx.x;   // 0 .. 512*256-1
    const int g  = blockIdx.y;                               // 0 .. 12
    const int xo = p & 511;                                  // lane-consecutive x
    const int yo = (p >> 9) << 1;                            // first of 2 rows

    // Per-block offy-sorted permutation: sperm[rank] = crop index.
    __shared__ int sperm[N_INNER];
    if (threadIdx.x < N_INNER) {
        const int cand = threadIdx.x;
        const int oyc  = __ldg(offy + cand);
        int rank = 0;
#pragma unroll
        for (int k = 0; k < N_INNER; ++k) {
            const int oyk = __ldg(offy + k);
            rank += (oyk < oyc) || (oyk == oyc && k < cand);
        }
        sperm[rank] = cand;
    }
    __syncthreads();

    int oy, ox, sz, j = -1;
    if (g == 0) { oy = 0; ox = 0; sz = 4096; }
    else {
        j  = sperm[g - 1];
        oy = __ldg(offy  + j);
        ox = __ldg(offx  + j);
        sz = __ldg(sizes + j);
    }

    const float s  = (float)sz;
    const float sc = s * (1.0f / 512.0f);   // exact pow2 scale

    const Taps tx = tap1d(ox, sz, s, sc, xo);
    const Taps ya = tap1d(oy, sz, s, sc, yo);
    const Taps yb = tap1d(oy, sz, s, sc, yo + 1);

    const size_t r0a = (size_t)ya.x0 * W;
    const size_t r1a = (size_t)ya.x1 * W;
    const size_t r0b = (size_t)yb.x0 * W;
    const size_t r1b = (size_t)yb.x1 * W;

    float va[3], vb[3];
#pragma unroll
    for (int c = 0; c < 3; ++c) {
        const float* base = img + (size_t)c * CH_STRIDE;
        const float a00 = __ldg(base + r0a + tx.x0);
        const float a01 = __ldg(base + r0a + tx.x1);
        const float a10 = __ldg(base + r1a + tx.x0);
        const float a11 = __ldg(base + r1a + tx.x1);
        const float b00 = __ldg(base + r0b + tx.x0);
        const float b01 = __ldg(base + r0b + tx.x1);
        const float b10 = __ldg(base + r1b + tx.x0);
        const float b11 = __ldg(base + r1b + tx.x1);

        const float atop = a00 + (a01 - a00) * tx.wx;
        const float abot = a10 + (a11 - a10) * tx.wx;
        const float btop = b00 + (b01 - b00) * tx.wx;
        const float bbot = b10 + (b11 - b10) * tx.wx;
        va[c] = atop + (abot - atop) * ya.wx;
        vb[c] = btop + (bbot - btop) * yb.wx;
    }

    if (g == 0) {
        const float ga = 0.2989f * va[0] + 0.587f * va[1] + 0.114f * va[2];
        const float gb = 0.2989f * vb[0] + 0.587f * vb[1] + 0.114f * vb[2];
        const size_t rowa = (size_t)yo * CUT;
        const size_t rowb = rowa + CUT;
        const size_t pfa = rowa + xo,  pra = rowa + (511 - xo);
        const size_t pfb = rowb + xo,  prb = rowb + (511 - xo);
#pragma unroll
        for (int c = 0; c < 3; ++c) {
            const size_t cp = (size_t)c * PLANE;
            __stcs(out + 0 * PLANE + cp + pfa, va[c]);   // img0 full
            __stcs(out + 0 * PLANE + cp + pfb, vb[c]);
            __stcs(out + 3 * PLANE + cp + pfa, ga);      // img1 gray
            __stcs(out + 3 * PLANE + cp + pfb, gb);
            __stcs(out + 6 * PLANE + cp + pra, va[c]);   // img2 flip
            __stcs(out + 6 * PLANE + cp + prb, vb[c]);
            __stcs(out + 9 * PLANE + cp + pra, ga);      // img3 gray-flip
            __stcs(out + 9 * PLANE + cp + prb, gb);
        }
    } else {
        if (j == 0) {   // crop 0 (original index) is grayed
            const float ga = 0.2989f * va[0] + 0.587f * va[1] + 0.114f * va[2];
            const float gb = 0.2989f * vb[0] + 0.587f * vb[1] + 0.114f * vb[2];
            va[0] = va[1] = va[2] = ga;
            vb[0] = vb[1] = vb[2] = gb;
        }
        const size_t obase = ((size_t)(j + 4) * 3) * PLANE + (size_t)yo * CUT + xo;
#pragma unroll
        for (int c = 0; c < 3; ++c) {
            __stcs(out + obase + (size_t)c * PLANE, va[c]);
            __stcs(out + obase + (size_t)c * PLANE + CUT, vb[c]);
        }
    }
}

extern "C" void kernel_launch(void* const* d_in, const int* in_sizes, int n_in,
                              void* d_out, int out_size)
{
    const float* img   = (const float*)d_in[0];
    // d_in[1] = t (unused)
    const int*   sizes = (const int*)d_in[2];
    const int*   offy  = (const int*)d_in[3];
    const int*   offx  = (const int*)d_in[4];
    float*       out   = (float*)d_out;

    dim3 block(256, 1, 1);
    dim3 grid((PLANE / 2) / 256, 13, 1);
    dango_cutouts_kernel<<<grid, block>>>(img, sizes, offy, offx, out);
}

// round 12
// speedup vs baseline: 3.2629x; 1.0007x over previous
#include <cuda_runtime.h>
#include <cstdint>

// DangoCutouts: 16 x (3,512,512) fp32 outputs from one (3,4096,4096) image.
// grid.y==0 : overview — one bilinear gather serves images 0,1,2,3.
// grid.y>=1 : random crops (crop 0 grayed), processed in offy-sorted order
//             (per-block smem permutation).
// 2 output pixels per thread in y. Explicit load/compute phase split:
// all 24 taps issued before any FMA -> max MLP. Streaming stores.

#define H 4096
#define W 4096
#define CUT 512
#define CH_STRIDE (4096u * 4096u)
#define PLANE (CUT * CUT)
#define N_INNER 12

struct Taps { int x0, x1; float wx; };

__device__ __forceinline__ Taps tap1d(int o, int size, float s, float sc, int i)
{
    float f = (float)o + (((float)i + 0.5f) * sc - 0.5f);
    f = fminf(fmaxf(f, (float)o), (float)o + s - 1.0f);
    Taps t;
    t.x0 = (int)floorf(f);
    t.x1 = min(t.x0 + 1, o + size - 1);
    t.wx = f - (float)t.x0;
    return t;
}

__global__ __launch_bounds__(256)
void dango_cutouts_kernel(const float* __restrict__ img,
                          const int*   __restrict__ sizes,
                          const int*   __restrict__ offy,
                          const int*   __restrict__ offx,
                          float*       __restrict__ out)
{
    const int p  = blockIdx.x * blockDim.x + threadIdx.x;   // 0 .. 512*256-1
    const int g  = blockIdx.y;                               // 0 .. 12
    const int xo = p & 511;                                  // lane-consecutive x
    const int yo = (p >> 9) << 1;                            // first of 2 rows

    // Per-block offy-sorted permutation: sperm[rank] = crop index.
    __shared__ int sperm[N_INNER];
    if (threadIdx.x < N_INNER) {
        const int cand = threadIdx.x;
        const int oyc  = __ldg(offy + cand);
        int rank = 0;
#pragma unroll
        for (int k = 0; k < N_INNER; ++k) {
            const int oyk = __ldg(offy + k);
            rank += (oyk < oyc) || (oyk == oyc && k < cand);
        }
        sperm[rank] = cand;
    }
    __syncthreads();

    int oy, ox, sz, j = -1;
    if (g == 0) { oy = 0; ox = 0; sz = 4096; }
    else {
        j  = sperm[g - 1];
        oy = __ldg(offy  + j);
        ox = __ldg(offx  + j);
        sz = __ldg(sizes + j);
    }

    const float s  = (float)sz;
    const float sc = s * (1.0f / 512.0f);   // exact pow2 scale

    const Taps tx = tap1d(ox, sz, s, sc, xo);
    const Taps ya = tap1d(oy, sz, s, sc, yo);
    const Taps yb = tap1d(oy, sz, s, sc, yo + 1);

    const size_t r0a = (size_t)ya.x0 * W;
    const size_t r1a = (size_t)ya.x1 * W;
    const size_t r0b = (size_t)yb.x0 * W;
    const size_t r1b = (size_t)yb.x1 * W;

    // ---- LOAD PHASE: all 24 taps issued back-to-back (max MLP) ----
    float a00[3], a01[3], a10[3], a11[3];
    float b00[3], b01[3], b10[3], b11[3];
#pragma unroll
    for (int c = 0; c < 3; ++c) {
        const float* base = img + (size_t)c * CH_STRIDE;
        a00[c] = __ldg(base + r0a + tx.x0);
        a01[c] = __ldg(base + r0a + tx.x1);
        a10[c] = __ldg(base + r1a + tx.x0);
        a11[c] = __ldg(base + r1a + tx.x1);
        b00[c] = __ldg(base + r0b + tx.x0);
        b01[c] = __ldg(base + r0b + tx.x1);
        b10[c] = __ldg(base + r1b + tx.x0);
        b11[c] = __ldg(base + r1b + tx.x1);
    }

    // ---- COMPUTE PHASE ----
    float va[3], vb[3];
#pragma unroll
    for (int c = 0; c < 3; ++c) {
        const float atop = a00[c] + (a01[c] - a00[c]) * tx.wx;
        const float abot = a10[c] + (a11[c] - a10[c]) * tx.wx;
        const float btop = b00[c] + (b01[c] - b00[c]) * tx.wx;
        const float bbot = b10[c] + (b11[c] - b10[c]) * tx.wx;
        va[c] = atop + (abot - atop) * ya.wx;
        vb[c] = btop + (bbot - btop) * yb.wx;
    }

    if (g == 0) {
        const float ga = 0.2989f * va[0] + 0.587f * va[1] + 0.114f * va[2];
        const float gb = 0.2989f * vb[0] + 0.587f * vb[1] + 0.114f * vb[2];
        const size_t rowa = (size_t)yo * CUT;
        const size_t rowb = rowa + CUT;
        const size_t pfa = rowa + xo,  pra = rowa + (511 - xo);
        const size_t pfb = rowb + xo,  prb = rowb + (511 - xo);
#pragma unroll
        for (int c = 0; c < 3; ++c) {
            const size_t cp = (size_t)c * PLANE;
            __stcs(out + 0 * PLANE + cp + pfa, va[c]);   // img0 full
            __stcs(out + 0 * PLANE + cp + pfb, vb[c]);
            __stcs(out + 3 * PLANE + cp + pfa, ga);      // img1 gray
            __stcs(out + 3 * PLANE + cp + pfb, gb);
            __stcs(out + 6 * PLANE + cp + pra, va[c]);   // img2 flip
            __stcs(out + 6 * PLANE + cp + prb, vb[c]);
            __stcs(out + 9 * PLANE + cp + pra, ga);      // img3 gray-flip
            __stcs(out + 9 * PLANE + cp + prb, gb);
        }
    } else {
        if (j == 0) {   // crop 0 (original index) is grayed
            const float ga = 0.2989f * va[0] + 0.587f * va[1] + 0.114f * va[2];
            const float gb = 0.2989f * vb[0] + 0.587f * vb[1] + 0.114f * vb[2];
            va[0] = va[1] = va[2] = ga;
            vb[0] = vb[1] = vb[2] = gb;
        }
        const size_t obase = ((size_t)(j + 4) * 3) * PLANE + (size_t)yo * CUT + xo;
#pragma unroll
        for (int c = 0; c < 3; ++c) {
            __stcs(out + obase + (size_t)c * PLANE, va[c]);
            __stcs(out + obase + (size_t)c * PLANE + CUT, vb[c]);
        }
    }
}

extern "C" void kernel_launch(void* const* d_in, const int* in_sizes, int n_in,
                              void* d_out, int out_size)
{
    const float* img   = (const float*)d_in[0];
    // d_in[1] = t (unused)
    const int*   sizes = (const int*)d_in[2];
    const int*   offy  = (const int*)d_in[3];
    const int*   offx  = (const int*)d_in[4];
    float*       out   = (float*)d_out;

    dim3 block(256, 1, 1);
    dim3 grid((PLANE / 2) / 256, 13, 1);
    dango_cutouts_kernel<<<grid, block>>>(img, sizes, offy, offx, out);
}